// round 8
// baseline (speedup 1.0000x reference)
#include <cuda_runtime.h>
#include <cuda_fp16.h>
#include <math.h>
#include <stdint.h>

#define BB 16
#define LS 2048
#define DD 128

// ---------------- scratch (device globals; no allocations) ----------------
__device__ __half g_Ph[(size_t)BB * LS * LS];          // P fp16 (134MB)
__device__ __half g_Qh[(size_t)BB * LS * DD];
__device__ __half g_Kh[(size_t)BB * LS * DD];
__device__ __half g_Vth[(size_t)BB * DD * LS];         // inv[k]*V transposed fp16
__device__ float g_part[(size_t)BB * LS * DD];         // gemm2 kz=1 partials
__device__ float g_dpart[BB * 16 * LS];                // per-(b,qt) column partials
__device__ float g_inv[BB * LS];
__device__ float g_cpart[BB * 16 * DD];
__device__ float g_c[BB * DD];
__device__ unsigned char g_m[BB * LS];
__device__ int g_qtflag[BB * 16];                      // 1 = whole q-tile masked
__device__ int g_maskmode;

// gemm1 smem: 4 tiles (Q0,Q1,K0,K1) 128x64 pitch-144B = 18432B each
#define G1_TB 18432
#define G1_SMEM 73728
// gemm2 smem: 2 stages x (P 128x64 18432 + V 64x64 9216) = 55296
#define G2_PV 27648
#define G2_SMEM 55296

// ---------------- helpers ---------------------------------------------------
__device__ __forceinline__ uint32_t smem_u32(const void* p) {
    uint32_t a;
    asm("{ .reg .u64 t; cvta.to.shared.u64 t, %1; cvt.u32.u64 %0, t; }" : "=r"(a) : "l"(p));
    return a;
}
__device__ __forceinline__ void ldsm4(uint32_t& r0, uint32_t& r1, uint32_t& r2,
                                      uint32_t& r3, uint32_t addr) {
    asm volatile("ldmatrix.sync.aligned.m8n8.x4.shared.b16 {%0,%1,%2,%3}, [%4];"
                 : "=r"(r0), "=r"(r1), "=r"(r2), "=r"(r3) : "r"(addr));
}
__device__ __forceinline__ void mma16816(float* c, const uint32_t* a, const uint32_t* b) {
    asm volatile("mma.sync.aligned.m16n8k16.row.col.f32.f16.f16.f32 "
                 "{%0,%1,%2,%3},{%4,%5,%6,%7},{%8,%9},{%0,%1,%2,%3};"
                 : "+f"(c[0]), "+f"(c[1]), "+f"(c[2]), "+f"(c[3])
                 : "r"(a[0]), "r"(a[1]), "r"(a[2]), "r"(a[3]), "r"(b[0]), "r"(b[1]));
}
#define CP_COMMIT() asm volatile("cp.async.commit_group;" ::: "memory")
#define CP_WAIT(n)  asm volatile("cp.async.wait_group %0;" :: "n"(n) : "memory")

template <int ROWS>
__device__ __forceinline__ void load_tile_async(const __half* __restrict__ g,
                                                size_t rowstride, char* st, int t) {
    uint32_t sa = smem_u32(st);
    #pragma unroll
    for (int it = 0; it < ROWS / 32; it++) {
        int idx = it * 256 + t;
        int r = idx >> 3, gp = idx & 7;
        asm volatile("cp.async.cg.shared.global [%0], [%1], 16;"
                     :: "r"(sa + r * 144 + gp * 16),
                        "l"(g + (size_t)r * rowstride + gp * 8) : "memory");
    }
}

// one mma pass, A 32x64 warp-tile x B^T (NG*32)x64, k=64
template <int NG>
__device__ __forceinline__ void mma_pass(char* pA, char* pB, int lane, int m0, int n0,
                                         float acc[2][2 * NG][4]) {
    int arow = (lane & 7) + ((lane >> 3) & 1) * 8;
    int acol = ((lane >> 4) & 1) * 8;
    int brow = (lane & 7) + ((lane >> 4) & 1) * 8;
    int bcol = ((lane >> 3) & 1) * 8;
    #pragma unroll
    for (int ks = 0; ks < 4; ks++) {
        int k0 = ks * 16;
        uint32_t a[8], bfr[4 * NG];
        #pragma unroll
        for (int mf = 0; mf < 2; mf++)
            ldsm4(a[mf*4], a[mf*4+1], a[mf*4+2], a[mf*4+3],
                  smem_u32(pA + (m0 + mf*16 + arow) * 144 + (k0 + acol) * 2));
        #pragma unroll
        for (int bg = 0; bg < NG; bg++)
            ldsm4(bfr[bg*4], bfr[bg*4+1], bfr[bg*4+2], bfr[bg*4+3],
                  smem_u32(pB + (n0 + bg*16 + brow) * 144 + (k0 + bcol) * 2));
        #pragma unroll
        for (int mf = 0; mf < 2; mf++)
            #pragma unroll
            for (int nf = 0; nf < 2 * NG; nf++)
                mma16816(acc[mf][nf], &a[mf*4], &bfr[(nf >> 1) * 4 + (nf & 1) * 2]);
    }
}

// ---------------- small kernels --------------------------------------------
__global__ void ta_detect(const unsigned int* m) {
    __shared__ int sF, sB;
    if (threadIdx.x == 0) { sF = 0; sB = 0; }
    __syncthreads();
    int f = 0, bg = 0;
    for (int i = threadIdx.x; i < (BB * LS) / 4; i += blockDim.x) {
        unsigned v = m[i];
        if (v == 0x3F800000u) f = 1; else if (v > 1u) bg = 1;
    }
    if (f) atomicOr(&sF, 1);
    if (bg) atomicOr(&sB, 1);
    __syncthreads();
    if (threadIdx.x == 0) g_maskmode = sF ? 2 : (sB ? 1 : 0);
}

__global__ void ta_buildmask(const void* mraw) {
    int t = threadIdx.x;
    int i = blockIdx.x * 256 + t;
    int mode = g_maskmode;
    unsigned char v = (mode == 1) ? (((const unsigned char*)mraw)[i] ? 1 : 0)
                                  : (((const unsigned int*)mraw)[i] ? 1 : 0);
    g_m[i] = v;
    __shared__ int cnt[2];
    if (t < 2) cnt[t] = 0;
    __syncthreads();
    if (!v) atomicAdd(&cnt[t >> 7], 1);
    __syncthreads();
    if (t < 2) g_qtflag[blockIdx.x * 2 + t] = (cnt[t] == 0);
}

__global__ void ta_prep(const int* __restrict__ ci, const float* __restrict__ Q,
                        const float* __restrict__ te) {
    int i = blockIdx.x * blockDim.x + threadIdx.x;   // over BB*LS*DD
    int row = i >> 7, c = i & 127;
    g_Qh[i] = __float2half_rn(Q[i]);
    g_Kh[i] = __float2half_rn(te[ci[row] * DD + c]);
}

__global__ void ta_dred() {
    int b = blockIdx.y, kt = blockIdx.x, t = threadIdx.x;
    int k = kt * 128 + t;
    float s = 0.f;
    for (int qt = kt; qt < 16; qt++) s += g_dpart[(b * 16 + qt) * LS + k];
    g_inv[b * LS + k] = (s != 0.f) ? 1.f / s : 0.f;
}

__global__ void ta_cpart(const float* __restrict__ V) {
    int b = blockIdx.y, ch = blockIdx.x, t = threadIdx.x;
    float s = 0.f;
    for (int k2 = 0; k2 < 128; k2++) {
        int k = ch * 128 + k2;
        if (g_inv[b * LS + k] == 0.f) s += V[((size_t)(b * LS + k)) * DD + t];
    }
    g_cpart[(b * 16 + ch) * DD + t] = s;
}

__global__ void ta_cfin() {
    int b = blockIdx.x, t = threadIdx.x;
    float s = 0.f;
    for (int ch = 0; ch < 16; ch++) s += g_cpart[(b * 16 + ch) * DD + t];
    g_c[b * DD + t] = s * (1.0f / (float)LS);
}

__global__ void ta_vt(const float* __restrict__ V) {
    __shared__ float sm[32][33];
    int b = blockIdx.z, k0 = blockIdx.x * 32, d0 = blockIdx.y * 32;
    int tx = threadIdx.x, ty = threadIdx.y;    // 32 x 8
    #pragma unroll
    for (int i = 0; i < 4; i++) {
        int kk = ty + i * 8;
        sm[kk][tx] = V[((size_t)(b * LS + k0 + kk)) * DD + d0 + tx];
    }
    __syncthreads();
    #pragma unroll
    for (int i = 0; i < 4; i++) {
        int dd_ = ty + i * 8;
        int k = k0 + tx;
        float v = sm[tx][dd_] * g_inv[b * LS + k];
        g_Vth[((size_t)(b * DD + d0 + dd_)) * LS + k] = __float2half_rn(v);
    }
}

// ---------------- GEMM1: S = Q.K^T, exp, colsum, P store (reg epilogue) ----
__global__ void __launch_bounds__(256, 2) ta_gemm1() {
    int x = blockIdx.x, b = blockIdx.y;
    int qt = (int)((sqrtf(8.f * x + 1.f) - 1.f) * 0.5f);
    while ((qt + 1) * (qt + 2) / 2 <= x) qt++;
    while (qt * (qt + 1) / 2 > x) qt--;
    int kt = x - qt * (qt + 1) / 2;
    int qb = qt << 7, kb = kt << 7;
    int t = threadIdx.x, lane = t & 31, wid = t >> 5;

    if (g_qtflag[b * 16 + qt]) {               // whole q-tile masked: P never read
        if (t < 128) g_dpart[(b * 16 + qt) * LS + kb + t] = 0.f;
        return;
    }

    extern __shared__ char smem[];
    int m0 = (wid & 3) * 32, n0 = (wid >> 2) * 64;
    float acc[2][8][4];
    #pragma unroll
    for (int i = 0; i < 2; i++)
        #pragma unroll
        for (int j = 0; j < 8; j++)
            #pragma unroll
            for (int v = 0; v < 4; v++) acc[i][j][v] = 0.f;

    const __half* Qh = g_Qh + ((size_t)(b * LS + qb)) * DD;
    const __half* Kh = g_Kh + ((size_t)(b * LS + kb)) * DD;

    load_tile_async<128>(Qh,      DD, smem + 0 * G1_TB, t);
    load_tile_async<128>(Qh + 64, DD, smem + 1 * G1_TB, t);
    load_tile_async<128>(Kh,      DD, smem + 2 * G1_TB, t);
    load_tile_async<128>(Kh + 64, DD, smem + 3 * G1_TB, t);
    CP_COMMIT();
    CP_WAIT(0);
    __syncthreads();
    mma_pass<4>(smem + 0 * G1_TB, smem + 2 * G1_TB, lane, m0, n0, acc);
    mma_pass<4>(smem + 1 * G1_TB, smem + 3 * G1_TB, lane, m0, n0, acc);

    // register epilogue: mask + exp, direct P store, column partials in regs
    int gid = lane >> 2, tid = lane & 3;
    const float invt = 1.0f / (sqrtf((float)DD) + 1e-6f);
    float colp[16];
    #pragma unroll
    for (int i = 0; i < 16; i++) colp[i] = 0.f;

    #pragma unroll
    for (int mf = 0; mf < 2; mf++)
        #pragma unroll
        for (int h = 0; h < 2; h++) {
            int m = m0 + mf * 16 + h * 8 + gid;
            int gq = qb + m;
            int pm = g_m[b * LS + gq];
            size_t rowb = ((size_t)(b * LS + gq)) * LS + kb;
            #pragma unroll
            for (int nf = 0; nf < 8; nf++) {
                int n = n0 + nf * 8 + tid * 2;
                int gk = kb + n;
                float v0 = acc[mf][nf][h * 2 + 0];
                float v1 = acc[mf][nf][h * 2 + 1];
                __half2 hp;
                hp.x = (pm || gk > gq)     ? __half(0.f) : __float2half_rn(__expf(v0 * invt));
                hp.y = (pm || gk + 1 > gq) ? __half(0.f) : __float2half_rn(__expf(v1 * invt));
                *(__half2*)&g_Ph[rowb + n] = hp;
                colp[nf * 2 + 0] += __half2float(hp.x);
                colp[nf * 2 + 1] += __half2float(hp.y);
            }
        }

    #pragma unroll
    for (int i = 0; i < 16; i++) {
        colp[i] += __shfl_xor_sync(0xFFFFFFFFu, colp[i], 4);
        colp[i] += __shfl_xor_sync(0xFFFFFFFFu, colp[i], 8);
        colp[i] += __shfl_xor_sync(0xFFFFFFFFu, colp[i], 16);
    }
    __syncthreads();
    float* red = (float*)smem;                 // [4 mwarps][128 cols]
    if (lane < 4) {
        int mw = wid & 3, nh = wid >> 2;
        #pragma unroll
        for (int nf = 0; nf < 8; nf++) {
            red[mw * 128 + nh * 64 + nf * 8 + lane * 2 + 0] = colp[nf * 2 + 0];
            red[mw * 128 + nh * 64 + nf * 8 + lane * 2 + 1] = colp[nf * 2 + 1];
        }
    }
    __syncthreads();
    if (t < 128)
        g_dpart[(b * 16 + qt) * LS + kb + t] =
            (red[t] + red[128 + t]) + (red[256 + t] + red[384 + t]);
}

// ---------------- GEMM2: out = P . (inv*V)^T + c, (qt, dh, kz) split -------
__global__ void __launch_bounds__(256, 3) ta_gemm2(float* __restrict__ out) {
    int x = blockIdx.x, b = blockIdx.y;
    int qt = 15 - (x >> 2), dh = (x >> 1) & 1, kz = x & 1;
    int qb = qt << 7, db = dh << 6;
    int t = threadIdx.x, lane = t & 31, wid = t >> 5;

    if (g_qtflag[b * 16 + qt]) {               // out rows = c (kz=0 only)
        if (kz == 0) {
            #pragma unroll
            for (int it = 0; it < 32; it++) {
                int idx = it * 256 + t;
                int r = idx >> 6, c = idx & 63;
                out[((size_t)(b * LS + qb + r)) * DD + db + c] = g_c[b * DD + db + c];
            }
        }
        return;
    }

    extern __shared__ char smem[];
    int m0 = (wid & 3) * 32, n0 = (wid >> 2) * 32;
    float acc[2][4][4];
    #pragma unroll
    for (int i = 0; i < 2; i++)
        #pragma unroll
        for (int j = 0; j < 4; j++)
            #pragma unroll
            for (int v = 0; v < 4; v++) acc[i][j][v] = 0.f;

    const __half* Ph = g_Ph + ((size_t)(b * LS + qb)) * LS;
    const __half* Vh = g_Vth + ((size_t)(b * DD + db)) * LS;

    int nck = (qt + 1) * 2;
    int half = nck >> 1;
    int c0 = kz ? half : 0, c1 = kz ? nck : half;

    load_tile_async<128>(Ph + c0 * 64, LS, smem + (c0 & 1) * G2_PV, t);
    load_tile_async<64>(Vh + c0 * 64, LS, smem + (c0 & 1) * G2_PV + G1_TB, t);
    CP_COMMIT();

    for (int ic = c0; ic < c1; ic++) {
        char* st = smem + (ic & 1) * G2_PV;
        if (ic + 1 < c1) {
            char* st2 = smem + ((ic + 1) & 1) * G2_PV;
            int kc2 = (ic + 1) * 64;
            load_tile_async<128>(Ph + kc2, LS, st2, t);
            load_tile_async<64>(Vh + kc2, LS, st2 + G1_TB, t);
            CP_COMMIT();
            CP_WAIT(1);
        } else {
            CP_WAIT(0);
        }
        __syncthreads();
        mma_pass<2>(st, st + G1_TB, lane, m0, n0, acc);
        __syncthreads();
    }

    int gid = lane >> 2, tid = lane & 3;
    #pragma unroll
    for (int mf = 0; mf < 2; mf++)
        #pragma unroll
        for (int h = 0; h < 2; h++) {
            int m = m0 + mf * 16 + h * 8 + gid;
            size_t ob = ((size_t)(b * LS + qb + m)) * DD;
            #pragma unroll
            for (int nf = 0; nf < 4; nf++) {
                int d = db + n0 + nf * 8 + tid * 2;
                float2 r;
                if (kz == 0) {
                    r.x = acc[mf][nf][h * 2 + 0] + g_c[b * DD + d];
                    r.y = acc[mf][nf][h * 2 + 1] + g_c[b * DD + d + 1];
                    *(float2*)&out[ob + d] = r;
                } else {
                    r.x = acc[mf][nf][h * 2 + 0];
                    r.y = acc[mf][nf][h * 2 + 1];
                    *(float2*)&g_part[ob + d] = r;
                }
            }
        }
}

// ---------------- add partials (skip masked q-tiles) ------------------------
__global__ void ta_add(float* __restrict__ out) {
    int qt = blockIdx.x, b = blockIdx.y, t = threadIdx.x;
    if (g_qtflag[b * 16 + qt]) return;
    size_t base = ((size_t)(b * LS + (qt << 7))) * DD;
    #pragma unroll
    for (int it = 0; it < 16; it++) {
        int idx = (it * 256 + t) * 4;          // 16384 floats per tile
        float4 a = *(float4*)&out[base + idx];
        float4 p = *(float4*)&g_part[base + idx];
        a.x += p.x; a.y += p.y; a.z += p.z; a.w += p.w;
        *(float4*)&out[base + idx] = a;
    }
}

// ---------------- launch ---------------------------------------------------
extern "C" void kernel_launch(void* const* d_in, const int* in_sizes, int n_in,
                              void* d_out, int out_size) {
    const int*   ci = (const int*)d_in[0];
    const float* qv = (const float*)d_in[1];   // cas_embs = Q = V
    const void*  mk = d_in[2];
    const float* te = (const float*)d_in[3];
    float* out = (float*)d_out;

    cudaFuncSetAttribute(ta_gemm1, cudaFuncAttributeMaxDynamicSharedMemorySize, G1_SMEM);
    cudaFuncSetAttribute(ta_gemm2, cudaFuncAttributeMaxDynamicSharedMemorySize, G2_SMEM);

    ta_detect<<<1, 256>>>((const unsigned int*)mk);
    ta_buildmask<<<(BB * LS) / 256, 256>>>(mk);
    ta_prep<<<(BB * LS * DD) / 256, 256>>>(ci, qv, te);
    ta_gemm1<<<dim3(136, BB), 256, G1_SMEM>>>();
    ta_dred<<<dim3(16, BB), 128>>>();
    ta_cpart<<<dim3(16, BB), 128>>>(qv);
    ta_cfin<<<BB, 128>>>();
    ta_vt<<<dim3(LS / 32, DD / 32, BB), dim3(32, 8)>>>(qv);
    ta_gemm2<<<dim3(64, BB), 256, G2_SMEM>>>(out);
    ta_add<<<dim3(16, BB), 256>>>(out);
}

// round 9
// speedup vs baseline: 1.0913x; 1.0913x over previous
#include <cuda_runtime.h>
#include <cuda_fp16.h>
#include <math.h>
#include <stdint.h>

#define BB 16
#define LS 2048
#define DD 128

// ---------------- scratch (device globals; no allocations) ----------------
__device__ __half g_Ph[(size_t)BB * LS * LS];          // P fp16 (134MB)
__device__ __half g_Qh[(size_t)BB * LS * DD];
__device__ __half g_Kh[(size_t)BB * LS * DD];
__device__ __half g_Vth[(size_t)BB * DD * LS];         // inv[k]*V transposed fp16
__device__ float g_dpart[BB * 16 * LS];                // per-(b,qt) column partials
__device__ float g_inv[BB * LS];
__device__ float g_cpart[BB * 16 * DD];
__device__ float g_c[BB * DD];
__device__ unsigned char g_m[BB * LS];
__device__ int g_qtflag[BB * 16];                      // 1 = whole q-tile masked
__device__ int g_maskmode;

// gemm1 smem: 4 tiles (Q0,Q1,K0,K1) 128x64 pitch-144B = 18432B each
#define G1_TB 18432
#define G1_SMEM 73728
// gemm2 smem: 2 stages x (P 128x64 18432 + V 64x64 9216) = 55296
#define G2_PV 27648
#define G2_SMEM 55296

// ---------------- helpers ---------------------------------------------------
__device__ __forceinline__ uint32_t smem_u32(const void* p) {
    uint32_t a;
    asm("{ .reg .u64 t; cvta.to.shared.u64 t, %1; cvt.u32.u64 %0, t; }" : "=r"(a) : "l"(p));
    return a;
}
__device__ __forceinline__ void ldsm4(uint32_t& r0, uint32_t& r1, uint32_t& r2,
                                      uint32_t& r3, uint32_t addr) {
    asm volatile("ldmatrix.sync.aligned.m8n8.x4.shared.b16 {%0,%1,%2,%3}, [%4];"
                 : "=r"(r0), "=r"(r1), "=r"(r2), "=r"(r3) : "r"(addr));
}
__device__ __forceinline__ void mma16816(float* c, const uint32_t* a, const uint32_t* b) {
    asm volatile("mma.sync.aligned.m16n8k16.row.col.f32.f16.f16.f32 "
                 "{%0,%1,%2,%3},{%4,%5,%6,%7},{%8,%9},{%0,%1,%2,%3};"
                 : "+f"(c[0]), "+f"(c[1]), "+f"(c[2]), "+f"(c[3])
                 : "r"(a[0]), "r"(a[1]), "r"(a[2]), "r"(a[3]), "r"(b[0]), "r"(b[1]));
}
#define CP_COMMIT() asm volatile("cp.async.commit_group;" ::: "memory")
#define CP_WAIT(n)  asm volatile("cp.async.wait_group %0;" :: "n"(n) : "memory")

template <int ROWS>
__device__ __forceinline__ void load_tile_async(const __half* __restrict__ g,
                                                size_t rowstride, char* st, int t) {
    uint32_t sa = smem_u32(st);
    #pragma unroll
    for (int it = 0; it < ROWS / 32; it++) {
        int idx = it * 256 + t;
        int r = idx >> 3, gp = idx & 7;
        asm volatile("cp.async.cg.shared.global [%0], [%1], 16;"
                     :: "r"(sa + r * 144 + gp * 16),
                        "l"(g + (size_t)r * rowstride + gp * 8) : "memory");
    }
}

// one mma pass, A 32x64 warp-tile x B^T (NG*32)x64, k=64
template <int NG>
__device__ __forceinline__ void mma_pass(char* pA, char* pB, int lane, int m0, int n0,
                                         float acc[2][2 * NG][4]) {
    int arow = (lane & 7) + ((lane >> 3) & 1) * 8;
    int acol = ((lane >> 4) & 1) * 8;
    int brow = (lane & 7) + ((lane >> 4) & 1) * 8;
    int bcol = ((lane >> 3) & 1) * 8;
    #pragma unroll
    for (int ks = 0; ks < 4; ks++) {
        int k0 = ks * 16;
        uint32_t a[8], bfr[4 * NG];
        #pragma unroll
        for (int mf = 0; mf < 2; mf++)
            ldsm4(a[mf*4], a[mf*4+1], a[mf*4+2], a[mf*4+3],
                  smem_u32(pA + (m0 + mf*16 + arow) * 144 + (k0 + acol) * 2));
        #pragma unroll
        for (int bg = 0; bg < NG; bg++)
            ldsm4(bfr[bg*4], bfr[bg*4+1], bfr[bg*4+2], bfr[bg*4+3],
                  smem_u32(pB + (n0 + bg*16 + brow) * 144 + (k0 + bcol) * 2));
        #pragma unroll
        for (int mf = 0; mf < 2; mf++)
            #pragma unroll
            for (int nf = 0; nf < 2 * NG; nf++)
                mma16816(acc[mf][nf], &a[mf*4], &bfr[(nf >> 1) * 4 + (nf & 1) * 2]);
    }
}

// ---------------- small kernels --------------------------------------------
__global__ void ta_detect(const unsigned int* m) {
    __shared__ int sF, sB;
    if (threadIdx.x == 0) { sF = 0; sB = 0; }
    __syncthreads();
    int f = 0, bg = 0;
    for (int i = threadIdx.x; i < (BB * LS) / 4; i += blockDim.x) {
        unsigned v = m[i];
        if (v == 0x3F800000u) f = 1; else if (v > 1u) bg = 1;
    }
    if (f) atomicOr(&sF, 1);
    if (bg) atomicOr(&sB, 1);
    __syncthreads();
    if (threadIdx.x == 0) g_maskmode = sF ? 2 : (sB ? 1 : 0);
}

__global__ void ta_buildmask(const void* mraw) {
    int t = threadIdx.x;
    int i = blockIdx.x * 256 + t;
    int mode = g_maskmode;
    unsigned char v = (mode == 1) ? (((const unsigned char*)mraw)[i] ? 1 : 0)
                                  : (((const unsigned int*)mraw)[i] ? 1 : 0);
    g_m[i] = v;
    __shared__ int cnt[2];
    if (t < 2) cnt[t] = 0;
    __syncthreads();
    if (!v) atomicAdd(&cnt[t >> 7], 1);
    __syncthreads();
    if (t < 2) g_qtflag[blockIdx.x * 2 + t] = (cnt[t] == 0);
}

// vectorized: 4 elems/thread (one row chunk)
__global__ void ta_prep(const int* __restrict__ ci, const float* __restrict__ Q,
                        const float* __restrict__ te) {
    int i4 = blockIdx.x * blockDim.x + threadIdx.x;   // over BB*LS*DD/4
    int base = i4 * 4;
    int row = base >> 7, c = base & 127;
    float4 q = *(const float4*)&Q[base];
    __half2 q0 = __floats2half2_rn(q.x, q.y);
    __half2 q1 = __floats2half2_rn(q.z, q.w);
    *(__half2*)&g_Qh[base] = q0;
    *(__half2*)&g_Qh[base + 2] = q1;
    float4 k = *(const float4*)&te[ci[row] * DD + c];
    __half2 k0 = __floats2half2_rn(k.x, k.y);
    __half2 k1 = __floats2half2_rn(k.z, k.w);
    *(__half2*)&g_Kh[base] = k0;
    *(__half2*)&g_Kh[base + 2] = k1;
}

// merged: denominators -> inv, plus degenerate-column partials for this k-chunk
__global__ void ta_dredc(const float* __restrict__ V) {
    int b = blockIdx.y, kt = blockIdx.x, t = threadIdx.x;
    int k = kt * 128 + t;
    float s = 0.f;
    for (int qt = kt; qt < 16; qt++) s += g_dpart[(b * 16 + qt) * LS + k];
    float inv = (s != 0.f) ? 1.f / s : 0.f;
    g_inv[b * LS + k] = inv;
    __shared__ unsigned char deg[128];
    deg[t] = (inv == 0.f);
    __syncthreads();
    float c = 0.f;
    for (int k2 = 0; k2 < 128; k2++)
        if (deg[k2]) c += V[((size_t)(b * LS + kt * 128 + k2)) * DD + t];
    g_cpart[(b * 16 + kt) * DD + t] = c;
}

__global__ void ta_cfin() {
    int b = blockIdx.x, t = threadIdx.x;
    float s = 0.f;
    for (int ch = 0; ch < 16; ch++) s += g_cpart[(b * 16 + ch) * DD + t];
    g_c[b * DD + t] = s * (1.0f / (float)LS);
}

__global__ void ta_vt(const float* __restrict__ V) {
    __shared__ float sm[32][33];
    int b = blockIdx.z, k0 = blockIdx.x * 32, d0 = blockIdx.y * 32;
    int tx = threadIdx.x, ty = threadIdx.y;    // 32 x 8
    #pragma unroll
    for (int i = 0; i < 4; i++) {
        int kk = ty + i * 8;
        sm[kk][tx] = V[((size_t)(b * LS + k0 + kk)) * DD + d0 + tx];
    }
    __syncthreads();
    #pragma unroll
    for (int i = 0; i < 4; i++) {
        int dd_ = ty + i * 8;
        int k = k0 + tx;
        float v = sm[tx][dd_] * g_inv[b * LS + k];
        g_Vth[((size_t)(b * DD + d0 + dd_)) * LS + k] = __float2half_rn(v);
    }
}

// ---------------- GEMM1: S = Q.K^T, exp, colsum, P store (pipelined) -------
__global__ void __launch_bounds__(256, 2) ta_gemm1() {
    int x = blockIdx.x, b = blockIdx.y;
    int qt = (int)((sqrtf(8.f * x + 1.f) - 1.f) * 0.5f);
    while ((qt + 1) * (qt + 2) / 2 <= x) qt++;
    while (qt * (qt + 1) / 2 > x) qt--;
    int kt = x - qt * (qt + 1) / 2;
    int qb = qt << 7, kb = kt << 7;
    int t = threadIdx.x, lane = t & 31, wid = t >> 5;

    if (g_qtflag[b * 16 + qt]) {               // whole q-tile masked: P never read
        if (t < 128) g_dpart[(b * 16 + qt) * LS + kb + t] = 0.f;
        return;
    }

    extern __shared__ char smem[];
    int m0 = (wid & 3) * 32, n0 = (wid >> 2) * 64;
    float acc[2][8][4];
    #pragma unroll
    for (int i = 0; i < 2; i++)
        #pragma unroll
        for (int j = 0; j < 8; j++)
            #pragma unroll
            for (int v = 0; v < 4; v++) acc[i][j][v] = 0.f;

    const __half* Qh = g_Qh + ((size_t)(b * LS + qb)) * DD;
    const __half* Kh = g_Kh + ((size_t)(b * LS + kb)) * DD;

    // two commit groups; overlap chunk0 mma with chunk1 loads
    load_tile_async<128>(Qh,      DD, smem + 0 * G1_TB, t);
    load_tile_async<128>(Kh,      DD, smem + 2 * G1_TB, t);
    CP_COMMIT();
    load_tile_async<128>(Qh + 64, DD, smem + 1 * G1_TB, t);
    load_tile_async<128>(Kh + 64, DD, smem + 3 * G1_TB, t);
    CP_COMMIT();
    CP_WAIT(1);
    __syncthreads();
    mma_pass<4>(smem + 0 * G1_TB, smem + 2 * G1_TB, lane, m0, n0, acc);
    CP_WAIT(0);
    __syncthreads();
    mma_pass<4>(smem + 1 * G1_TB, smem + 3 * G1_TB, lane, m0, n0, acc);

    // register epilogue: mask + exp, direct P store, column partials in regs
    int gid = lane >> 2, tid = lane & 3;
    const float invt = 1.0f / (sqrtf((float)DD) + 1e-6f);
    float colp[16];
    #pragma unroll
    for (int i = 0; i < 16; i++) colp[i] = 0.f;

    #pragma unroll
    for (int mf = 0; mf < 2; mf++)
        #pragma unroll
        for (int h = 0; h < 2; h++) {
            int m = m0 + mf * 16 + h * 8 + gid;
            int gq = qb + m;
            int pm = g_m[b * LS + gq];
            size_t rowb = ((size_t)(b * LS + gq)) * LS + kb;
            #pragma unroll
            for (int nf = 0; nf < 8; nf++) {
                int n = n0 + nf * 8 + tid * 2;
                int gk = kb + n;
                float v0 = acc[mf][nf][h * 2 + 0];
                float v1 = acc[mf][nf][h * 2 + 1];
                __half2 hp;
                hp.x = (pm || gk > gq)     ? __half(0.f) : __float2half_rn(__expf(v0 * invt));
                hp.y = (pm || gk + 1 > gq) ? __half(0.f) : __float2half_rn(__expf(v1 * invt));
                *(__half2*)&g_Ph[rowb + n] = hp;
                colp[nf * 2 + 0] += __half2float(hp.x);
                colp[nf * 2 + 1] += __half2float(hp.y);
            }
        }

    #pragma unroll
    for (int i = 0; i < 16; i++) {
        colp[i] += __shfl_xor_sync(0xFFFFFFFFu, colp[i], 4);
        colp[i] += __shfl_xor_sync(0xFFFFFFFFu, colp[i], 8);
        colp[i] += __shfl_xor_sync(0xFFFFFFFFu, colp[i], 16);
    }
    __syncthreads();
    float* red = (float*)smem;                 // [4 mwarps][128 cols]
    if (lane < 4) {
        int mw = wid & 3, nh = wid >> 2;
        #pragma unroll
        for (int nf = 0; nf < 8; nf++) {
            red[mw * 128 + nh * 64 + nf * 8 + lane * 2 + 0] = colp[nf * 2 + 0];
            red[mw * 128 + nh * 64 + nf * 8 + lane * 2 + 1] = colp[nf * 2 + 1];
        }
    }
    __syncthreads();
    if (t < 128)
        g_dpart[(b * 16 + qt) * LS + kb + t] =
            (red[t] + red[128 + t]) + (red[256 + t] + red[384 + t]);
}

// ---------------- GEMM2: out = P . (inv*V)^T + c, pipelined, d-split -------
__global__ void __launch_bounds__(256, 3) ta_gemm2(float* __restrict__ out) {
    int qt = 15 - (blockIdx.x >> 1), dh = blockIdx.x & 1, b = blockIdx.y;
    int qb = qt << 7, db = dh << 6;
    int t = threadIdx.x, lane = t & 31, wid = t >> 5;

    if (g_qtflag[b * 16 + qt]) {               // out rows = c
        #pragma unroll
        for (int it = 0; it < 32; it++) {
            int idx = it * 256 + t;
            int r = idx >> 6, c = idx & 63;
            out[((size_t)(b * LS + qb + r)) * DD + db + c] = g_c[b * DD + db + c];
        }
        return;
    }

    extern __shared__ char smem[];
    int m0 = (wid & 3) * 32, n0 = (wid >> 2) * 32;
    float acc[2][4][4];
    #pragma unroll
    for (int i = 0; i < 2; i++)
        #pragma unroll
        for (int j = 0; j < 4; j++)
            #pragma unroll
            for (int v = 0; v < 4; v++) acc[i][j][v] = 0.f;

    const __half* Ph = g_Ph + ((size_t)(b * LS + qb)) * LS;
    const __half* Vh = g_Vth + ((size_t)(b * DD + db)) * LS;

    int nck = (qt + 1) * 2;
    load_tile_async<128>(Ph, LS, smem, t);
    load_tile_async<64>(Vh, LS, smem + G1_TB, t);
    CP_COMMIT();

    for (int ic = 0; ic < nck; ic++) {
        char* st = smem + (ic & 1) * G2_PV;
        if (ic + 1 < nck) {
            char* st2 = smem + ((ic + 1) & 1) * G2_PV;
            int kc2 = (ic + 1) * 64;
            load_tile_async<128>(Ph + kc2, LS, st2, t);
            load_tile_async<64>(Vh + kc2, LS, st2 + G1_TB, t);
            CP_COMMIT();
            CP_WAIT(1);
        } else {
            CP_WAIT(0);
        }
        __syncthreads();
        mma_pass<2>(st, st + G1_TB, lane, m0, n0, acc);
        __syncthreads();
    }

    int gid = lane >> 2, tid = lane & 3;
    #pragma unroll
    for (int mf = 0; mf < 2; mf++)
        #pragma unroll
        for (int h = 0; h < 2; h++) {
            int m = m0 + mf * 16 + h * 8 + gid;
            size_t ob = ((size_t)(b * LS + qb + m)) * DD;
            #pragma unroll
            for (int nf = 0; nf < 4; nf++) {
                int d = db + n0 + nf * 8 + tid * 2;
                float2 r;
                r.x = acc[mf][nf][h * 2 + 0] + g_c[b * DD + d];
                r.y = acc[mf][nf][h * 2 + 1] + g_c[b * DD + d + 1];
                *(float2*)&out[ob + d] = r;
            }
        }
}

// ---------------- launch ---------------------------------------------------
extern "C" void kernel_launch(void* const* d_in, const int* in_sizes, int n_in,
                              void* d_out, int out_size) {
    const int*   ci = (const int*)d_in[0];
    const float* qv = (const float*)d_in[1];   // cas_embs = Q = V
    const void*  mk = d_in[2];
    const float* te = (const float*)d_in[3];
    float* out = (float*)d_out;

    cudaFuncSetAttribute(ta_gemm1, cudaFuncAttributeMaxDynamicSharedMemorySize, G1_SMEM);
    cudaFuncSetAttribute(ta_gemm2, cudaFuncAttributeMaxDynamicSharedMemorySize, G2_SMEM);

    ta_detect<<<1, 256>>>((const unsigned int*)mk);
    ta_buildmask<<<(BB * LS) / 256, 256>>>(mk);
    ta_prep<<<(BB * LS * DD) / 1024, 256>>>(ci, qv, te);
    ta_gemm1<<<dim3(136, BB), 256, G1_SMEM>>>();
    ta_dredc<<<dim3(16, BB), 128>>>(qv);
    ta_cfin<<<BB, 128>>>();
    ta_vt<<<dim3(LS / 32, DD / 32, BB), dim3(32, 8)>>>(qv);
    ta_gemm2<<<dim3(32, BB), 256, G2_SMEM>>>(out);
}

// round 10
// speedup vs baseline: 1.1261x; 1.0319x over previous
#include <cuda_runtime.h>
#include <cuda_fp16.h>
#include <math.h>
#include <stdint.h>

#define BB 16
#define LS 2048
#define DD 128

// ---------------- scratch (device globals; no allocations) ----------------
__device__ __half g_Ph[(size_t)BB * LS * LS];          // P fp16 (134MB)
__device__ __half g_Qh[(size_t)BB * LS * DD];
__device__ __half g_Kh[(size_t)BB * LS * DD];
__device__ __half g_Vth[(size_t)BB * DD * LS];         // inv[k]*V transposed fp16
__device__ float g_dpart[BB * 16 * LS];                // per-(b,qt) column partials
__device__ float g_inv[BB * LS];
__device__ float g_cpart[BB * 16 * DD];
__device__ float g_c[BB * DD];
__device__ unsigned char g_m[BB * LS];
__device__ int g_qtflag[BB * 16];                      // 1 = whole q-tile masked
__device__ int g_maskmode;

// gemm1 smem: Q0,Q1 (128x64, 18432B) + K0,K1 (64x64, 9216B) = 55296
#define G1_Q0 0
#define G1_Q1 18432
#define G1_K0 36864
#define G1_K1 46080
#define G1_SMEM 55296
// gemm2 smem: 2 stages x (P 128x64 18432 + V 64x64 9216) = 55296
#define G2_TB 18432
#define G2_PV 27648
#define G2_SMEM 55296

// ---------------- helpers ---------------------------------------------------
__device__ __forceinline__ uint32_t smem_u32(const void* p) {
    uint32_t a;
    asm("{ .reg .u64 t; cvta.to.shared.u64 t, %1; cvt.u32.u64 %0, t; }" : "=r"(a) : "l"(p));
    return a;
}
__device__ __forceinline__ void ldsm4(uint32_t& r0, uint32_t& r1, uint32_t& r2,
                                      uint32_t& r3, uint32_t addr) {
    asm volatile("ldmatrix.sync.aligned.m8n8.x4.shared.b16 {%0,%1,%2,%3}, [%4];"
                 : "=r"(r0), "=r"(r1), "=r"(r2), "=r"(r3) : "r"(addr));
}
__device__ __forceinline__ void mma16816(float* c, const uint32_t* a, const uint32_t* b) {
    asm volatile("mma.sync.aligned.m16n8k16.row.col.f32.f16.f16.f32 "
                 "{%0,%1,%2,%3},{%4,%5,%6,%7},{%8,%9},{%0,%1,%2,%3};"
                 : "+f"(c[0]), "+f"(c[1]), "+f"(c[2]), "+f"(c[3])
                 : "r"(a[0]), "r"(a[1]), "r"(a[2]), "r"(a[3]), "r"(b[0]), "r"(b[1]));
}
#define CP_COMMIT() asm volatile("cp.async.commit_group;" ::: "memory")
#define CP_WAIT(n)  asm volatile("cp.async.wait_group %0;" :: "n"(n) : "memory")

template <int ROWS>
__device__ __forceinline__ void load_tile_async(const __half* __restrict__ g,
                                                size_t rowstride, char* st, int t) {
    uint32_t sa = smem_u32(st);
    #pragma unroll
    for (int it = 0; it < ROWS / 32; it++) {
        int idx = it * 256 + t;
        int r = idx >> 3, gp = idx & 7;
        asm volatile("cp.async.cg.shared.global [%0], [%1], 16;"
                     :: "r"(sa + r * 144 + gp * 16),
                        "l"(g + (size_t)r * rowstride + gp * 8) : "memory");
    }
}

// one mma pass, A 32x64 warp-tile x B^T (NG*32... actually NG*16 rows group) k=64
template <int NG>
__device__ __forceinline__ void mma_pass(char* pA, char* pB, int lane, int m0, int n0,
                                         float acc[2][2 * NG][4]) {
    int arow = (lane & 7) + ((lane >> 3) & 1) * 8;
    int acol = ((lane >> 4) & 1) * 8;
    int brow = (lane & 7) + ((lane >> 4) & 1) * 8;
    int bcol = ((lane >> 3) & 1) * 8;
    #pragma unroll
    for (int ks = 0; ks < 4; ks++) {
        int k0 = ks * 16;
        uint32_t a[8], bfr[4 * NG];
        #pragma unroll
        for (int mf = 0; mf < 2; mf++)
            ldsm4(a[mf*4], a[mf*4+1], a[mf*4+2], a[mf*4+3],
                  smem_u32(pA + (m0 + mf*16 + arow) * 144 + (k0 + acol) * 2));
        #pragma unroll
        for (int bg = 0; bg < NG; bg++)
            ldsm4(bfr[bg*4], bfr[bg*4+1], bfr[bg*4+2], bfr[bg*4+3],
                  smem_u32(pB + (n0 + bg*16 + brow) * 144 + (k0 + bcol) * 2));
        #pragma unroll
        for (int mf = 0; mf < 2; mf++)
            #pragma unroll
            for (int nf = 0; nf < 2 * NG; nf++)
                mma16816(acc[mf][nf], &a[mf*4], &bfr[(nf >> 1) * 4 + (nf & 1) * 2]);
    }
}

// ---------------- small kernels --------------------------------------------
__global__ void ta_detect(const unsigned int* m) {
    __shared__ int sF, sB;
    if (threadIdx.x == 0) { sF = 0; sB = 0; }
    __syncthreads();
    int f = 0, bg = 0;
    for (int i = threadIdx.x; i < (BB * LS) / 4; i += blockDim.x) {
        unsigned v = m[i];
        if (v == 0x3F800000u) f = 1; else if (v > 1u) bg = 1;
    }
    if (f) atomicOr(&sF, 1);
    if (bg) atomicOr(&sB, 1);
    __syncthreads();
    if (threadIdx.x == 0) g_maskmode = sF ? 2 : (sB ? 1 : 0);
}

__global__ void ta_buildmask(const void* mraw) {
    int t = threadIdx.x;
    int i = blockIdx.x * 256 + t;
    int mode = g_maskmode;
    unsigned char v = (mode == 1) ? (((const unsigned char*)mraw)[i] ? 1 : 0)
                                  : (((const unsigned int*)mraw)[i] ? 1 : 0);
    g_m[i] = v;
    __shared__ int cnt[2];
    if (t < 2) cnt[t] = 0;
    __syncthreads();
    if (!v) atomicAdd(&cnt[t >> 7], 1);
    __syncthreads();
    if (t < 2) g_qtflag[blockIdx.x * 2 + t] = (cnt[t] == 0);
}

__global__ void ta_prep(const int* __restrict__ ci, const float* __restrict__ Q,
                        const float* __restrict__ te) {
    int i4 = blockIdx.x * blockDim.x + threadIdx.x;   // over BB*LS*DD/4
    int base = i4 * 4;
    int row = base >> 7, c = base & 127;
    float4 q = *(const float4*)&Q[base];
    *(__half2*)&g_Qh[base]     = __floats2half2_rn(q.x, q.y);
    *(__half2*)&g_Qh[base + 2] = __floats2half2_rn(q.z, q.w);
    float4 k = *(const float4*)&te[ci[row] * DD + c];
    *(__half2*)&g_Kh[base]     = __floats2half2_rn(k.x, k.y);
    *(__half2*)&g_Kh[base + 2] = __floats2half2_rn(k.z, k.w);
}

// merged: denominators -> inv, plus degenerate-column partials for this k-chunk
__global__ void ta_dredc(const float* __restrict__ V) {
    int b = blockIdx.y, kt = blockIdx.x, t = threadIdx.x;
    int k = kt * 128 + t;
    float s = 0.f;
    for (int qt = kt; qt < 16; qt++) s += g_dpart[(b * 16 + qt) * LS + k];
    float inv = (s != 0.f) ? 1.f / s : 0.f;
    g_inv[b * LS + k] = inv;
    __shared__ unsigned char deg[128];
    deg[t] = (inv == 0.f);
    __syncthreads();
    float c = 0.f;
    for (int k2 = 0; k2 < 128; k2++)
        if (deg[k2]) c += V[((size_t)(b * LS + kt * 128 + k2)) * DD + t];
    g_cpart[(b * 16 + kt) * DD + t] = c;
}

__global__ void ta_cfin() {
    int b = blockIdx.x, t = threadIdx.x;
    float s = 0.f;
    for (int ch = 0; ch < 16; ch++) s += g_cpart[(b * 16 + ch) * DD + t];
    g_c[b * DD + t] = s * (1.0f / (float)LS);
}

__global__ void ta_vt(const float* __restrict__ V) {
    __shared__ float sm[32][33];
    int b = blockIdx.z, k0 = blockIdx.x * 32, d0 = blockIdx.y * 32;
    int tx = threadIdx.x, ty = threadIdx.y;    // 32 x 8
    #pragma unroll
    for (int i = 0; i < 4; i++) {
        int kk = ty + i * 8;
        sm[kk][tx] = V[((size_t)(b * LS + k0 + kk)) * DD + d0 + tx];
    }
    __syncthreads();
    #pragma unroll
    for (int i = 0; i < 4; i++) {
        int dd_ = ty + i * 8;
        int k = k0 + tx;
        float v = sm[tx][dd_] * g_inv[b * LS + k];
        g_Vth[((size_t)(b * DD + d0 + dd_)) * LS + k] = __float2half_rn(v);
    }
}

// ---------------- GEMM1: 128q x 64k tiles, 3 CTAs/SM -----------------------
__global__ void __launch_bounds__(256, 3) ta_gemm1() {
    int x = blockIdx.x, b = blockIdx.y;
    int y = x >> 1, kh = x & 1;
    int qt = (int)((sqrtf(8.f * y + 1.f) - 1.f) * 0.5f);
    while ((qt + 1) * (qt + 2) / 2 <= y) qt++;
    while (qt * (qt + 1) / 2 > y) qt--;
    int kt = y - qt * (qt + 1) / 2;
    int qb = qt << 7, kb = (kt << 7) + (kh << 6);
    int t = threadIdx.x, lane = t & 31, wid = t >> 5;

    if (g_qtflag[b * 16 + qt]) {               // whole q-tile masked: P never read
        if (t < 64) g_dpart[(b * 16 + qt) * LS + kb + t] = 0.f;
        return;
    }

    extern __shared__ char smem[];
    int m0 = (wid & 3) * 32, n0 = (wid >> 2) * 32;
    float acc[2][4][4];
    #pragma unroll
    for (int i = 0; i < 2; i++)
        #pragma unroll
        for (int j = 0; j < 4; j++)
            #pragma unroll
            for (int v = 0; v < 4; v++) acc[i][j][v] = 0.f;

    const __half* Qh = g_Qh + ((size_t)(b * LS + qb)) * DD;
    const __half* Kh = g_Kh + ((size_t)(b * LS + kb)) * DD;

    // two commit groups; overlap d-chunk0 mma with chunk1 loads
    load_tile_async<128>(Qh,      DD, smem + G1_Q0, t);
    load_tile_async<64>(Kh,       DD, smem + G1_K0, t);
    CP_COMMIT();
    load_tile_async<128>(Qh + 64, DD, smem + G1_Q1, t);
    load_tile_async<64>(Kh + 64,  DD, smem + G1_K1, t);
    CP_COMMIT();
    CP_WAIT(1);
    __syncthreads();
    mma_pass<2>(smem + G1_Q0, smem + G1_K0, lane, m0, n0, acc);
    CP_WAIT(0);
    __syncthreads();
    mma_pass<2>(smem + G1_Q1, smem + G1_K1, lane, m0, n0, acc);

    // register epilogue: mask + exp, direct P store, column partials in regs
    int gid = lane >> 2, tid = lane & 3;
    const float invt = 1.0f / (sqrtf((float)DD) + 1e-6f);
    float colp[8];
    #pragma unroll
    for (int i = 0; i < 8; i++) colp[i] = 0.f;

    #pragma unroll
    for (int mf = 0; mf < 2; mf++)
        #pragma unroll
        for (int h = 0; h < 2; h++) {
            int m = m0 + mf * 16 + h * 8 + gid;
            int gq = qb + m;
            int pm = g_m[b * LS + gq];
            size_t rowb = ((size_t)(b * LS + gq)) * LS + kb;
            #pragma unroll
            for (int nf = 0; nf < 4; nf++) {
                int n = n0 + nf * 8 + tid * 2;
                int gk = kb + n;
                float v0 = acc[mf][nf][h * 2 + 0];
                float v1 = acc[mf][nf][h * 2 + 1];
                __half2 hp;
                hp.x = (pm || gk > gq)     ? __half(0.f) : __float2half_rn(__expf(v0 * invt));
                hp.y = (pm || gk + 1 > gq) ? __half(0.f) : __float2half_rn(__expf(v1 * invt));
                *(__half2*)&g_Ph[rowb + n] = hp;
                colp[nf * 2 + 0] += __half2float(hp.x);
                colp[nf * 2 + 1] += __half2float(hp.y);
            }
        }

    #pragma unroll
    for (int i = 0; i < 8; i++) {
        colp[i] += __shfl_xor_sync(0xFFFFFFFFu, colp[i], 4);
        colp[i] += __shfl_xor_sync(0xFFFFFFFFu, colp[i], 8);
        colp[i] += __shfl_xor_sync(0xFFFFFFFFu, colp[i], 16);
    }
    __syncthreads();
    float* red = (float*)smem;                 // [4 mwarps][64 cols]
    if (lane < 4) {
        int mw = wid & 3, nh = wid >> 2;
        #pragma unroll
        for (int nf = 0; nf < 4; nf++) {
            red[mw * 64 + nh * 32 + nf * 8 + lane * 2 + 0] = colp[nf * 2 + 0];
            red[mw * 64 + nh * 32 + nf * 8 + lane * 2 + 1] = colp[nf * 2 + 1];
        }
    }
    __syncthreads();
    if (t < 64)
        g_dpart[(b * 16 + qt) * LS + kb + t] =
            (red[t] + red[64 + t]) + (red[128 + t] + red[192 + t]);
}

// ---------------- GEMM2: out = P . (inv*V)^T + c, pipelined, d-split -------
__global__ void __launch_bounds__(256, 3) ta_gemm2(float* __restrict__ out) {
    int qt = 15 - (blockIdx.x >> 1), dh = blockIdx.x & 1, b = blockIdx.y;
    int qb = qt << 7, db = dh << 6;
    int t = threadIdx.x, lane = t & 31, wid = t >> 5;

    if (g_qtflag[b * 16 + qt]) {               // out rows = c
        #pragma unroll
        for (int it = 0; it < 32; it++) {
            int idx = it * 256 + t;
            int r = idx >> 6, c = idx & 63;
            out[((size_t)(b * LS + qb + r)) * DD + db + c] = g_c[b * DD + db + c];
        }
        return;
    }

    extern __shared__ char smem[];
    int m0 = (wid & 3) * 32, n0 = (wid >> 2) * 32;
    float acc[2][4][4];
    #pragma unroll
    for (int i = 0; i < 2; i++)
        #pragma unroll
        for (int j = 0; j < 4; j++)
            #pragma unroll
            for (int v = 0; v < 4; v++) acc[i][j][v] = 0.f;

    const __half* Ph = g_Ph + ((size_t)(b * LS + qb)) * LS;
    const __half* Vh = g_Vth + ((size_t)(b * DD + db)) * LS;

    int nck = (qt + 1) * 2;
    load_tile_async<128>(Ph, LS, smem, t);
    load_tile_async<64>(Vh, LS, smem + G2_TB, t);
    CP_COMMIT();

    for (int ic = 0; ic < nck; ic++) {
        char* st = smem + (ic & 1) * G2_PV;
        if (ic + 1 < nck) {
            char* st2 = smem + ((ic + 1) & 1) * G2_PV;
            int kc2 = (ic + 1) * 64;
            load_tile_async<128>(Ph + kc2, LS, st2, t);
            load_tile_async<64>(Vh + kc2, LS, st2 + G2_TB, t);
            CP_COMMIT();
            CP_WAIT(1);
        } else {
            CP_WAIT(0);
        }
        __syncthreads();
        mma_pass<2>(st, st + G2_TB, lane, m0, n0, acc);
        __syncthreads();
    }

    int gid = lane >> 2, tid = lane & 3;
    #pragma unroll
    for (int mf = 0; mf < 2; mf++)
        #pragma unroll
        for (int h = 0; h < 2; h++) {
            int m = m0 + mf * 16 + h * 8 + gid;
            size_t ob = ((size_t)(b * LS + qb + m)) * DD;
            #pragma unroll
            for (int nf = 0; nf < 4; nf++) {
                int d = db + n0 + nf * 8 + tid * 2;
                float2 r;
                r.x = acc[mf][nf][h * 2 + 0] + g_c[b * DD + d];
                r.y = acc[mf][nf][h * 2 + 1] + g_c[b * DD + d + 1];
                *(float2*)&out[ob + d] = r;
            }
        }
}

// ---------------- launch ---------------------------------------------------
extern "C" void kernel_launch(void* const* d_in, const int* in_sizes, int n_in,
                              void* d_out, int out_size) {
    const int*   ci = (const int*)d_in[0];
    const float* qv = (const float*)d_in[1];   // cas_embs = Q = V
    const void*  mk = d_in[2];
    const float* te = (const float*)d_in[3];
    float* out = (float*)d_out;

    cudaFuncSetAttribute(ta_gemm1, cudaFuncAttributeMaxDynamicSharedMemorySize, G1_SMEM);
    cudaFuncSetAttribute(ta_gemm2, cudaFuncAttributeMaxDynamicSharedMemorySize, G2_SMEM);

    ta_detect<<<1, 256>>>((const unsigned int*)mk);
    ta_buildmask<<<(BB * LS) / 256, 256>>>(mk);
    ta_prep<<<(BB * LS * DD) / 1024, 256>>>(ci, qv, te);
    ta_gemm1<<<dim3(272, BB), 256, G1_SMEM>>>();
    ta_dredc<<<dim3(16, BB), 128>>>(qv);
    ta_cfin<<<BB, 128>>>();
    ta_vt<<<dim3(LS / 32, DD / 32, BB), dim3(32, 8)>>>(qv);
    ta_gemm2<<<dim3(32, BB), 256, G2_SMEM>>>(out);
}